// round 2
// baseline (speedup 1.0000x reference)
#include <cuda_runtime.h>
#include <cuda_bf16.h>
#include <cstdint>

#define NB     8        // batch
#define NPOS   21824    // total positions across 5 levels
#define NCLS   80
#define KTOP   1000
#define NBIN   8192
#define CAP    4096
#define IOU_TH 0.5f

// ---------------- scratch (static device globals; no allocation) ----------------
__device__ float    g_score[NB * NPOS];
__device__ int      g_kind [NB * NPOS];
__device__ float4   g_boxes[NB * NPOS];
__device__ float    g_topBox  [NB * KTOP * 4];
__device__ int      g_topKind [NB * KTOP];
__device__ float    g_topScore[NB * KTOP];
__device__ unsigned g_mask    [NB * KTOP * 32];

// ---------------- K1: class max/argmax + box decode ----------------
__global__ void k_decode(
    const float* __restrict__ c0, const float* __restrict__ c1,
    const float* __restrict__ c2, const float* __restrict__ c3,
    const float* __restrict__ c4,
    const float* __restrict__ r0, const float* __restrict__ r1,
    const float* __restrict__ r2, const float* __restrict__ r3,
    const float* __restrict__ r4)
{
    int pos = blockIdx.x * blockDim.x + threadIdx.x;
    int b   = blockIdx.y;
    if (pos >= NPOS) return;

    int lvl, local, logw;
    float stride;
    if      (pos < 16384) { lvl = 0; local = pos;         logw = 7; stride = 8.f;   }
    else if (pos < 20480) { lvl = 1; local = pos - 16384; logw = 6; stride = 16.f;  }
    else if (pos < 21504) { lvl = 2; local = pos - 20480; logw = 5; stride = 32.f;  }
    else if (pos < 21760) { lvl = 3; local = pos - 21504; logw = 4; stride = 64.f;  }
    else                  { lvl = 4; local = pos - 21760; logw = 3; stride = 128.f; }
    int hw = 1 << (2 * logw);

    const float* clsA[5] = { c0, c1, c2, c3, c4 };
    const float* regA[5] = { r0, r1, r2, r3, r4 };

    const float* cls = clsA[lvl] + (size_t)b * NCLS * hw + local;
    float best = cls[0];
    int   bi   = 0;
    #pragma unroll 8
    for (int c = 1; c < NCLS; c++) {
        float v = cls[(size_t)c * hw];
        if (v > best) { best = v; bi = c; }
    }
    float score = (best > 0.05f) ? best : 0.0f;

    const float* rg = regA[lvl] + (size_t)b * 4 * hw + local;
    // stride is a power of two -> products are exact, decode bit-exact vs ref
    float dl = rg[0]      * stride;
    float dt = rg[hw]     * stride;
    float dr = rg[2 * hw] * stride;
    float db = rg[3 * hw] * stride;

    int w = 1 << logw;
    int y = local >> logw;
    int x = local & (w - 1);
    float cx = ((float)x + 0.5f) * stride;
    float cy = ((float)y + 0.5f) * stride;

    float4 box = make_float4(cx - dl, cy - dt, cx + dr, cy + db);

    int o = b * NPOS + pos;
    g_score[o] = score;
    g_kind[o]  = bi;
    g_boxes[o] = box;
}

// ---------------- K2: exact top-1000 per image (hist threshold + bitonic) ------
__global__ void __launch_bounds__(1024) k_topk(float* __restrict__ out)
{
    const int b   = blockIdx.x;
    const int tid = threadIdx.x;

    __shared__ unsigned long long buf[CAP];   // 32 KB, aliased: first as hist[8192]
    __shared__ unsigned gsum[1024];
    __shared__ unsigned ssum[32];
    __shared__ int s_t;
    __shared__ int s_cnt;

    unsigned* hist = (unsigned*)buf;

    // phase 1: histogram of positive scores
    for (int i = tid; i < NBIN; i += 1024) hist[i] = 0;
    __syncthreads();
    const float* sc_base = &g_score[b * NPOS];
    for (int i = tid; i < NPOS; i += 1024) {
        float sc = sc_base[i];
        if (sc > 0.0f) {
            int bin = (int)(sc * (float)NBIN);
            if (bin > NBIN - 1) bin = NBIN - 1;
            atomicAdd(&hist[bin], 1u);
        }
    }
    __syncthreads();

    // phase 2: find threshold bin t: count(bin>=t) >= KTOP, minimal coverage
    {   // group sums over reversed bins (r = 0 at top bin 8191)
        unsigned s = 0;
        int g = tid;
        #pragma unroll
        for (int r = 0; r < 8; r++) s += hist[NBIN - 1 - (8 * g + r)];
        gsum[g] = s;
    }
    __syncthreads();
    if (tid < 32) {
        unsigned s = 0;
        #pragma unroll
        for (int q = 0; q < 32; q++) s += gsum[tid * 32 + q];
        ssum[tid] = s;
    }
    __syncthreads();
    if (tid == 0) {
        unsigned cum = 0;
        int t = 0;
        bool found = false;
        for (int w = 0; w < 32 && !found; w++) {
            if (cum + ssum[w] < KTOP) { cum += ssum[w]; continue; }
            for (int g = w * 32; g < w * 32 + 32 && !found; g++) {
                if (cum + gsum[g] < KTOP) { cum += gsum[g]; continue; }
                for (int r = g * 8; r < g * 8 + 8; r++) {
                    cum += hist[NBIN - 1 - r];
                    if (cum >= KTOP) { t = NBIN - 1 - r; found = true; break; }
                }
            }
        }
        s_t   = found ? t : 0;
        s_cnt = 0;
    }
    __syncthreads();
    const int t = s_t;

    // phase 3: compact candidates with bin >= t as sortable 64-bit keys
    for (int i = tid; i < CAP; i += 1024) buf[i] = 0ULL;
    __syncthreads();
    for (int i = tid; i < NPOS; i += 1024) {
        float sc = sc_base[i];
        if (sc > 0.0f) {
            int bin = (int)(sc * (float)NBIN);
            if (bin > NBIN - 1) bin = NBIN - 1;
            if (bin >= t) {
                int k = atomicAdd(&s_cnt, 1);
                if (k < CAP) {
                    unsigned long long key =
                        ((unsigned long long)__float_as_uint(sc) << 32) |
                        (unsigned long long)(0xFFFFFFFFu - (unsigned)i);
                    buf[k] = key;
                }
            }
        }
    }
    __syncthreads();

    // phase 4: bitonic sort CAP elements, descending
    for (int k = 2; k <= CAP; k <<= 1) {
        for (int j = k >> 1; j > 0; j >>= 1) {
            for (int idx = tid; idx < CAP; idx += 1024) {
                int ixj = idx ^ j;
                if (ixj > idx) {
                    unsigned long long a = buf[idx];
                    unsigned long long c = buf[ixj];
                    bool sw = ((idx & k) == 0) ? (a < c) : (a > c);
                    if (sw) { buf[idx] = c; buf[ixj] = a; }
                }
            }
            __syncthreads();
        }
    }

    // phase 5: emit top-1000 rows (cols 0..4); stash scratch for NMS
    for (int i = tid; i < KTOP; i += 1024) {
        unsigned long long key = buf[i];
        float    sc  = __uint_as_float((unsigned)(key >> 32));
        unsigned pos = 0xFFFFFFFFu - (unsigned)(key & 0xFFFFFFFFull);
        if (key == 0ULL) { sc = 0.0f; pos = 0; }
        int src = b * NPOS + (int)pos;
        float4 bx = g_boxes[src];
        int    kd = g_kind[src];

        int row = b * KTOP + i;
        out[row * 6 + 0] = bx.x;
        out[row * 6 + 1] = bx.y;
        out[row * 6 + 2] = bx.z;
        out[row * 6 + 3] = bx.w;
        out[row * 6 + 4] = (float)kd;

        g_topBox[row * 4 + 0] = bx.x;
        g_topBox[row * 4 + 1] = bx.y;
        g_topBox[row * 4 + 2] = bx.z;
        g_topBox[row * 4 + 3] = bx.w;
        g_topKind[row]  = kd;
        g_topScore[row] = sc;
    }
}

// ---------------- K3: class-aware greedy NMS (bitmask + serial warp scan) ------
__global__ void __launch_bounds__(1024) k_nms(float* __restrict__ out)
{
    const int b   = blockIdx.x;
    const int tid = threadIdx.x;

    __shared__ float sx1[KTOP], sy1[KTOP], sx2[KTOP], sy2[KTOP], sar[KTOP];
    __shared__ int   skd[KTOP];
    __shared__ unsigned sRem[32];

    for (int i = tid; i < KTOP; i += 1024) {
        int row = b * KTOP + i;
        float x1 = g_topBox[row * 4 + 0];
        float y1 = g_topBox[row * 4 + 1];
        float x2 = g_topBox[row * 4 + 2];
        float y2 = g_topBox[row * 4 + 3];
        sx1[i] = x1; sy1[i] = y1; sx2[i] = x2; sy2[i] = y2;
        sar[i] = fmaxf(x2 - x1, 0.0f) * fmaxf(y2 - y1, 0.0f);
        skd[i] = g_topKind[row];
    }
    __syncthreads();

    // suppression bitmask: mask[i][w] bit jj set iff j = w*32+jj is suppressed by i
    unsigned* mrow = &g_mask[b * KTOP * 32];
    for (int task = tid; task < KTOP * 32; task += 1024) {
        int i = task >> 5;
        int w = task & 31;
        float x1 = sx1[i], y1 = sy1[i], x2 = sx2[i], y2 = sy2[i], ai = sar[i];
        int kd = skd[i];
        unsigned bits = 0;
        int j0 = w * 32;
        #pragma unroll
        for (int jj = 0; jj < 32; jj++) {
            int j = j0 + jj;
            if (j < KTOP && j > i && skd[j] == kd) {
                float xx1 = fmaxf(x1, sx1[j]);
                float yy1 = fmaxf(y1, sy1[j]);
                float xx2 = fminf(x2, sx2[j]);
                float yy2 = fminf(y2, sy2[j]);
                float inter = fmaxf(xx2 - xx1, 0.0f) * fmaxf(yy2 - yy1, 0.0f);
                // denominator op order matches reference: ((ai+aj)-inter)+1e-9
                float iou = inter / (((ai + sar[j]) - inter) + 1e-9f);
                if (iou > IOU_TH) bits |= (1u << jj);
            }
        }
        mrow[i * 32 + w] = bits;
    }
    __syncthreads();   // global writes visible within block after barrier

    if (tid < 32) {
        unsigned removed = 0;
        unsigned cur = mrow[tid];               // row 0 prefetch
        for (int i = 0; i < KTOP; i++) {
            unsigned nxt = (i + 1 < KTOP) ? mrow[(i + 1) * 32 + tid] : 0u;
            unsigned rb = __shfl_sync(0xFFFFFFFFu, removed, i >> 5);
            if (!((rb >> (i & 31)) & 1u)) removed |= cur;
            cur = nxt;
        }
        sRem[tid] = removed;
    }
    __syncthreads();

    for (int i = tid; i < KTOP; i += 1024) {
        bool kept = !((sRem[i >> 5] >> (i & 31)) & 1u);
        float sc = g_topScore[b * KTOP + i];
        out[(b * KTOP + i) * 6 + 5] = (kept && sc > 0.0f) ? sc : 0.0f;
    }
}

// ---------------- launch ----------------
extern "C" void kernel_launch(void* const* d_in, const int* in_sizes, int n_in,
                              void* d_out, int out_size)
{
    static const int hw[5] = { 16384, 4096, 1024, 256, 64 };
    const float* clsP[5] = { 0, 0, 0, 0, 0 };
    const float* regP[5] = { 0, 0, 0, 0, 0 };
    bool cntSeen[5] = { false, false, false, false, false };

    // Identify inputs by element count. cls sizes are unique.
    // cnt_i and reg_{i+1} collide in size; in both plausible metadata orders
    // cnt_i appears before reg_{i+1}, so first occurrence -> cnt (unused),
    // second -> reg.
    for (int i = 0; i < n_in; i++) {
        long long s = in_sizes[i];
        bool matched = false;
        for (int l = 0; l < 5 && !matched; l++)
            if (s == (long long)NB * NCLS * hw[l]) { clsP[l] = (const float*)d_in[i]; matched = true; }
        if (matched) continue;
        for (int l = 0; l < 5 && !matched; l++)
            if (s == (long long)NB * hw[l] && !cntSeen[l]) { cntSeen[l] = true; matched = true; }
        if (matched) continue;
        for (int l = 0; l < 5 && !matched; l++)
            if (s == (long long)NB * 4 * hw[l] && !regP[l]) { regP[l] = (const float*)d_in[i]; matched = true; }
    }

    float* out = (float*)d_out;

    dim3 g1((NPOS + 255) / 256, NB);
    k_decode<<<g1, 256>>>(clsP[0], clsP[1], clsP[2], clsP[3], clsP[4],
                          regP[0], regP[1], regP[2], regP[3], regP[4]);
    k_topk<<<NB, 1024>>>(out);
    k_nms <<<NB, 1024>>>(out);
}

// round 4
// speedup vs baseline: 4.9300x; 4.9300x over previous
#include <cuda_runtime.h>
#include <cstdint>

#define NB     8
#define NPOS   21824
#define NG     (NPOS / 4)     // 5456 position-groups of 4
#define NCLS   80
#define KTOP   1000
#define NBIN   8192
#define CAP    2048
#define IOU_TH 0.5f

// ---------------- scratch ----------------
__device__ __align__(16) float g_score[NB * NPOS];
__device__ __align__(16) int   g_kind [NB * NPOS];
__device__ float4              g_boxes[NB * NPOS];

// ---------------- K1: class max/argmax + box decode (float4, 4 pos/thread) ----
__global__ void k_decode(
    const float* __restrict__ c0, const float* __restrict__ c1,
    const float* __restrict__ c2, const float* __restrict__ c3,
    const float* __restrict__ c4,
    const float* __restrict__ r0, const float* __restrict__ r1,
    const float* __restrict__ r2, const float* __restrict__ r3,
    const float* __restrict__ r4)
{
    int g = blockIdx.x * blockDim.x + threadIdx.x;
    if (g >= NG) return;
    int b   = blockIdx.y;
    int pos = g << 2;

    int lvl, local, logw;
    float stride;
    if      (pos < 16384) { lvl = 0; local = pos;         logw = 7; stride = 8.f;   }
    else if (pos < 20480) { lvl = 1; local = pos - 16384; logw = 6; stride = 16.f;  }
    else if (pos < 21504) { lvl = 2; local = pos - 20480; logw = 5; stride = 32.f;  }
    else if (pos < 21760) { lvl = 3; local = pos - 21504; logw = 4; stride = 64.f;  }
    else                  { lvl = 4; local = pos - 21760; logw = 3; stride = 128.f; }
    int hw    = 1 << (2 * logw);
    int cstep = hw >> 2;   // class stride in float4 units

    const float* clsA[5] = { c0, c1, c2, c3, c4 };
    const float* regA[5] = { r0, r1, r2, r3, r4 };

    const float4* cls = (const float4*)(clsA[lvl] + (size_t)b * NCLS * hw + local);
    float4 bv = cls[0];
    int k0 = 0, k1 = 0, k2 = 0, k3 = 0;
    #pragma unroll 8
    for (int c = 1; c < NCLS; c++) {
        float4 v = cls[(size_t)c * cstep];
        if (v.x > bv.x) { bv.x = v.x; k0 = c; }
        if (v.y > bv.y) { bv.y = v.y; k1 = c; }
        if (v.z > bv.z) { bv.z = v.z; k2 = c; }
        if (v.w > bv.w) { bv.w = v.w; k3 = c; }
    }

    const float4* rg = (const float4*)(regA[lvl] + (size_t)b * 4 * hw + local);
    float4 dl4 = rg[0];
    float4 dt4 = rg[cstep];
    float4 dr4 = rg[2 * cstep];
    float4 db4 = rg[3 * cstep];

    int w = 1 << logw;
    int y = local >> logw;
    int x = local & (w - 1);
    float cy = ((float)y + 0.5f) * stride;

    int o = b * NPOS + pos;
    // stride is a power of two: products exact -> bit-exact decode
    {
        float cx = ((float)(x + 0) + 0.5f) * stride;
        g_boxes[o + 0] = make_float4(cx - dl4.x * stride, cy - dt4.x * stride,
                                     cx + dr4.x * stride, cy + db4.x * stride);
        cx = ((float)(x + 1) + 0.5f) * stride;
        g_boxes[o + 1] = make_float4(cx - dl4.y * stride, cy - dt4.y * stride,
                                     cx + dr4.y * stride, cy + db4.y * stride);
        cx = ((float)(x + 2) + 0.5f) * stride;
        g_boxes[o + 2] = make_float4(cx - dl4.z * stride, cy - dt4.z * stride,
                                     cx + dr4.z * stride, cy + db4.z * stride);
        cx = ((float)(x + 3) + 0.5f) * stride;
        g_boxes[o + 3] = make_float4(cx - dl4.w * stride, cy - dt4.w * stride,
                                     cx + dr4.w * stride, cy + db4.w * stride);
    }
    float s0 = (bv.x > 0.05f) ? bv.x : 0.0f;
    float s1 = (bv.y > 0.05f) ? bv.y : 0.0f;
    float s2 = (bv.z > 0.05f) ? bv.z : 0.0f;
    float s3 = (bv.w > 0.05f) ? bv.w : 0.0f;
    *(float4*)&g_score[o] = make_float4(s0, s1, s2, s3);
    *(int4*)&g_kind[o]    = make_int4(k0, k1, k2, k3);
}

// ---------------- K2: fused exact top-1000 + class-aware NMS per image --------
// dynamic smem layout (bytes):
//   [0,      16384)  buf[CAP] u64 keys            (aliases lower hist)
//   [16384,  26624)  kindBits[80][32]             (aliases upper hist; built later)
//   [0,      32768)  hist[8192] u32 (phases 1-2 only)
//   [32768, 160768)  mask[KTOP][32] u32
//   [160768,184768)  sx1/sy1/sx2/sy2/sar (f32) + skd (i32), 1000 each
//   [184768,188864)  gsum[1024] u32 (phase 2), reused as row-nonzero flags
#define SM_KB    16384
#define SM_MASK  32768
#define SM_X1   160768
#define SM_Y1   164768
#define SM_X2   168768
#define SM_Y2   172768
#define SM_AR   176768
#define SM_KD   180768
#define SM_GS   184768
#define SMEM_BYTES 188864

__global__ void __launch_bounds__(1024) k_topk_nms(float* __restrict__ out)
{
    const int b   = blockIdx.x;
    const int tid = threadIdx.x;

    extern __shared__ char sm[];
    unsigned*            hist     = (unsigned*)sm;
    unsigned long long*  buf      = (unsigned long long*)sm;
    unsigned*            kindBits = (unsigned*)(sm + SM_KB);
    unsigned*            mask     = (unsigned*)(sm + SM_MASK);
    float*               sx1      = (float*)(sm + SM_X1);
    float*               sy1      = (float*)(sm + SM_Y1);
    float*               sx2      = (float*)(sm + SM_X2);
    float*               sy2      = (float*)(sm + SM_Y2);
    float*               sar      = (float*)(sm + SM_AR);
    int*                 skd      = (int*)(sm + SM_KD);
    unsigned*            gsum     = (unsigned*)(sm + SM_GS);

    __shared__ unsigned ssum[32];
    __shared__ unsigned sRem[32];
    __shared__ int s_t, s_cnt;

    // ---- phase 1: histogram of positive scores ----
    for (int i = tid; i < NBIN; i += 1024) hist[i] = 0;
    __syncthreads();
    const float* sc_base = &g_score[b * NPOS];
    for (int i = tid; i < NPOS; i += 1024) {
        float sc = sc_base[i];
        if (sc > 0.0f) {
            int bin = (int)(sc * (float)NBIN);
            if (bin > NBIN - 1) bin = NBIN - 1;
            atomicAdd(&hist[bin], 1u);
        }
    }
    __syncthreads();

    // ---- phase 2: threshold bin (minimal t s.t. count(bin>=t) >= KTOP) ----
    {
        unsigned s = 0;
        #pragma unroll
        for (int r = 0; r < 8; r++) s += hist[NBIN - 1 - (8 * tid + r)];
        gsum[tid] = s;
    }
    __syncthreads();
    if (tid < 32) {
        unsigned s = 0;
        #pragma unroll
        for (int q = 0; q < 32; q++) s += gsum[tid * 32 + q];
        ssum[tid] = s;
    }
    __syncthreads();
    if (tid == 0) {
        unsigned cum = 0;
        int t = 0;
        bool found = false;
        for (int w = 0; w < 32 && !found; w++) {
            if (cum + ssum[w] < KTOP) { cum += ssum[w]; continue; }
            for (int g = w * 32; g < w * 32 + 32 && !found; g++) {
                if (cum + gsum[g] < KTOP) { cum += gsum[g]; continue; }
                for (int r = g * 8; r < g * 8 + 8; r++) {
                    cum += hist[NBIN - 1 - r];
                    if (cum >= KTOP) { t = NBIN - 1 - r; found = true; break; }
                }
            }
        }
        s_t = found ? t : 0;
        s_cnt = 0;
    }
    __syncthreads();
    const int t = s_t;

    // ---- phase 3: compact candidates (bin >= t) as sortable u64 keys ----
    // (overwrites hist; also zero kindBits here)
    for (int i = tid; i < CAP; i += 1024) buf[i] = 0ULL;
    if (tid < NCLS * 32) kindBits[tid + 0] = 0u;
    if (tid + 1024 < NCLS * 32) kindBits[tid + 1024] = 0u;
    if (tid + 2048 < NCLS * 32) kindBits[tid + 2048] = 0u;
    __syncthreads();
    for (int i = tid; i < NPOS; i += 1024) {
        float sc = sc_base[i];
        if (sc > 0.0f) {
            int bin = (int)(sc * (float)NBIN);
            if (bin > NBIN - 1) bin = NBIN - 1;
            if (bin >= t) {
                int k = atomicAdd(&s_cnt, 1);
                if (k < CAP) {
                    buf[k] = ((unsigned long long)__float_as_uint(sc) << 32) |
                             (unsigned long long)(0xFFFFFFFFu - (unsigned)i);
                }
            }
        }
    }
    __syncthreads();

    // ---- phase 4: bitonic sort CAP=2048 descending (1 CE per thread/pass) ----
    for (int k = 2; k <= CAP; k <<= 1) {
        for (int j = k >> 1; j > 0; j >>= 1) {
            for (int idx = tid; idx < CAP; idx += 1024) {
                int ixj = idx ^ j;
                if (ixj > idx) {
                    unsigned long long a = buf[idx];
                    unsigned long long c = buf[ixj];
                    bool sw = ((idx & k) == 0) ? (a < c) : (a > c);
                    if (sw) { buf[idx] = c; buf[ixj] = a; }
                }
            }
            __syncthreads();
        }
    }

    // ---- phase 5: emit cols 0..4, stage NMS data, build class bitmasks ----
    if (tid < KTOP) {
        int i = tid;
        unsigned long long key = buf[i];
        unsigned pos = 0xFFFFFFFFu - (unsigned)(key & 0xFFFFFFFFull);
        if (key == 0ULL) pos = 0;
        int src = b * NPOS + (int)pos;
        float4 bx = g_boxes[src];
        int    kd = g_kind[src];

        int row = b * KTOP + i;
        out[row * 6 + 0] = bx.x;
        out[row * 6 + 1] = bx.y;
        out[row * 6 + 2] = bx.z;
        out[row * 6 + 3] = bx.w;
        out[row * 6 + 4] = (float)kd;

        sx1[i] = bx.x; sy1[i] = bx.y; sx2[i] = bx.z; sy2[i] = bx.w;
        sar[i] = fmaxf(bx.z - bx.x, 0.0f) * fmaxf(bx.w - bx.y, 0.0f);
        skd[i] = kd;
        atomicOr(&kindBits[kd * 32 + (i >> 5)], 1u << (i & 31));
    }
    __syncthreads();

    // ---- phase 6: suppression bitmask, gated by same-class membership ----
    for (int task = tid; task < KTOP * 32; task += 1024) {
        int i = task >> 5;
        int w = task & 31;
        int kd = skd[i];
        unsigned cand = kindBits[kd * 32 + w];
        int iw = i >> 5;
        if (w < iw)       cand = 0u;
        else if (w == iw) cand &= ~((2u << (i & 31)) - 1u);   // bits j>i only
        unsigned bits = 0u;
        if (cand) {
            float x1 = sx1[i], y1 = sy1[i], x2 = sx2[i], y2 = sy2[i], ai = sar[i];
            do {
                int jj = __ffs(cand) - 1;
                cand &= cand - 1u;
                int j = w * 32 + jj;
                float xx1 = fmaxf(x1, sx1[j]);
                float yy1 = fmaxf(y1, sy1[j]);
                float xx2 = fminf(x2, sx2[j]);
                float yy2 = fminf(y2, sy2[j]);
                float inter = fmaxf(xx2 - xx1, 0.0f) * fmaxf(yy2 - yy1, 0.0f);
                // op order matches reference: ((ai+aj)-inter)+1e-9
                float iou = inter / (((ai + sar[j]) - inter) + 1e-9f);
                if (iou > IOU_TH) bits |= (1u << jj);
            } while (cand);
        }
        mask[i * 32 + w] = bits;
    }
    __syncthreads();

    // ---- phase 7: row-nonzero flags ----
    if (tid < KTOP) {
        unsigned nz = 0u;
        #pragma unroll 8
        for (int w = 0; w < 32; w++) nz |= mask[tid * 32 + w];
        gsum[tid] = nz;
    }
    __syncthreads();

    // ---- phase 8: greedy scan over nonzero rows only (warp 0) ----
    if (tid < 32) {
        unsigned removed = 0u;
        for (int base = 0; base < KTOP; base += 32) {
            int r0 = base + tid;
            unsigned f = (r0 < KTOP) ? gsum[r0] : 0u;
            unsigned bal = __ballot_sync(0xFFFFFFFFu, f != 0u);
            while (bal) {
                int r = base + __ffs(bal) - 1;
                bal &= bal - 1u;
                unsigned rb = __shfl_sync(0xFFFFFFFFu, removed, r >> 5);
                if (!((rb >> (r & 31)) & 1u))
                    removed |= mask[r * 32 + tid];
            }
        }
        sRem[tid] = removed;
    }
    __syncthreads();

    // ---- phase 9: final scores ----
    if (tid < KTOP) {
        int i = tid;
        bool kept = !((sRem[i >> 5] >> (i & 31)) & 1u);
        float sc = __uint_as_float((unsigned)(buf[i] >> 32));
        out[(b * KTOP + i) * 6 + 5] = (kept && sc > 0.0f) ? sc : 0.0f;
    }
}

// ---------------- launch ----------------
extern "C" void kernel_launch(void* const* d_in, const int* in_sizes, int n_in,
                              void* d_out, int out_size)
{
    static const int hw[5] = { 16384, 4096, 1024, 256, 64 };
    const float* clsP[5] = { 0, 0, 0, 0, 0 };
    const float* regP[5] = { 0, 0, 0, 0, 0 };
    bool cntSeen[5] = { false, false, false, false, false };

    for (int i = 0; i < n_in; i++) {
        long long s = in_sizes[i];
        bool matched = false;
        for (int l = 0; l < 5 && !matched; l++)
            if (s == (long long)NB * NCLS * hw[l]) { clsP[l] = (const float*)d_in[i]; matched = true; }
        if (matched) continue;
        for (int l = 0; l < 5 && !matched; l++)
            if (s == (long long)NB * hw[l] && !cntSeen[l]) { cntSeen[l] = true; matched = true; }
        if (matched) continue;
        for (int l = 0; l < 5 && !matched; l++)
            if (s == (long long)NB * 4 * hw[l] && !regP[l]) { regP[l] = (const float*)d_in[i]; matched = true; }
    }

    float* out = (float*)d_out;

    cudaFuncSetAttribute(k_topk_nms, cudaFuncAttributeMaxDynamicSharedMemorySize, SMEM_BYTES);

    dim3 g1((NG + 127) / 128, NB);
    k_decode<<<g1, 128>>>(clsP[0], clsP[1], clsP[2], clsP[3], clsP[4],
                          regP[0], regP[1], regP[2], regP[3], regP[4]);
    k_topk_nms<<<NB, 1024, SMEM_BYTES>>>(out);
}

// round 5
// speedup vs baseline: 5.4292x; 1.1013x over previous
#include <cuda_runtime.h>
#include <cstdint>

#define NB     8
#define NPOS   21824
#define NG     (NPOS / 4)
#define NCLS   80
#define KTOP   1000
#define NBIN   8192
#define CAP    2048
#define IOU_TH 0.5f

// ---------------- scratch ----------------
__device__ __align__(16) float g_score[NB * NPOS];
__device__ __align__(16) int   g_kind [NB * NPOS];
__device__ float4              g_boxes[NB * NPOS];
__device__ unsigned            g_hist [NB * NBIN];   // zero at load; K2 re-zeros

// ---------------- K1: class max/argmax + decode + global score histogram -----
__global__ void k_decode(
    const float* __restrict__ c0, const float* __restrict__ c1,
    const float* __restrict__ c2, const float* __restrict__ c3,
    const float* __restrict__ c4,
    const float* __restrict__ r0, const float* __restrict__ r1,
    const float* __restrict__ r2, const float* __restrict__ r3,
    const float* __restrict__ r4)
{
    int g = blockIdx.x * blockDim.x + threadIdx.x;
    if (g >= NG) return;
    int b   = blockIdx.y;
    int pos = g << 2;

    int lvl, local, logw;
    float stride;
    if      (pos < 16384) { lvl = 0; local = pos;         logw = 7; stride = 8.f;   }
    else if (pos < 20480) { lvl = 1; local = pos - 16384; logw = 6; stride = 16.f;  }
    else if (pos < 21504) { lvl = 2; local = pos - 20480; logw = 5; stride = 32.f;  }
    else if (pos < 21760) { lvl = 3; local = pos - 21504; logw = 4; stride = 64.f;  }
    else                  { lvl = 4; local = pos - 21760; logw = 3; stride = 128.f; }
    int hw    = 1 << (2 * logw);
    int cstep = hw >> 2;

    const float* clsA[5] = { c0, c1, c2, c3, c4 };
    const float* regA[5] = { r0, r1, r2, r3, r4 };

    const float4* cls = (const float4*)(clsA[lvl] + (size_t)b * NCLS * hw + local);
    float4 bv = cls[0];
    int k0 = 0, k1 = 0, k2 = 0, k3 = 0;
    #pragma unroll 8
    for (int c = 1; c < NCLS; c++) {
        float4 v = cls[(size_t)c * cstep];
        if (v.x > bv.x) { bv.x = v.x; k0 = c; }
        if (v.y > bv.y) { bv.y = v.y; k1 = c; }
        if (v.z > bv.z) { bv.z = v.z; k2 = c; }
        if (v.w > bv.w) { bv.w = v.w; k3 = c; }
    }

    const float4* rg = (const float4*)(regA[lvl] + (size_t)b * 4 * hw + local);
    float4 dl4 = rg[0];
    float4 dt4 = rg[cstep];
    float4 dr4 = rg[2 * cstep];
    float4 db4 = rg[3 * cstep];

    int w = 1 << logw;
    int y = local >> logw;
    int x = local & (w - 1);
    float cy = ((float)y + 0.5f) * stride;

    int o = b * NPOS + pos;
    {
        float cx = ((float)(x + 0) + 0.5f) * stride;
        g_boxes[o + 0] = make_float4(cx - dl4.x * stride, cy - dt4.x * stride,
                                     cx + dr4.x * stride, cy + db4.x * stride);
        cx = ((float)(x + 1) + 0.5f) * stride;
        g_boxes[o + 1] = make_float4(cx - dl4.y * stride, cy - dt4.y * stride,
                                     cx + dr4.y * stride, cy + db4.y * stride);
        cx = ((float)(x + 2) + 0.5f) * stride;
        g_boxes[o + 2] = make_float4(cx - dl4.z * stride, cy - dt4.z * stride,
                                     cx + dr4.z * stride, cy + db4.z * stride);
        cx = ((float)(x + 3) + 0.5f) * stride;
        g_boxes[o + 3] = make_float4(cx - dl4.w * stride, cy - dt4.w * stride,
                                     cx + dr4.w * stride, cy + db4.w * stride);
    }
    float s0 = (bv.x > 0.05f) ? bv.x : 0.0f;
    float s1 = (bv.y > 0.05f) ? bv.y : 0.0f;
    float s2 = (bv.z > 0.05f) ? bv.z : 0.0f;
    float s3 = (bv.w > 0.05f) ? bv.w : 0.0f;
    *(float4*)&g_score[o] = make_float4(s0, s1, s2, s3);
    *(int4*)&g_kind[o]    = make_int4(k0, k1, k2, k3);

    unsigned* hb = &g_hist[b * NBIN];
    if (s0 > 0.0f) { int bn = (int)(s0 * (float)NBIN); if (bn > NBIN-1) bn = NBIN-1; atomicAdd(&hb[bn], 1u); }
    if (s1 > 0.0f) { int bn = (int)(s1 * (float)NBIN); if (bn > NBIN-1) bn = NBIN-1; atomicAdd(&hb[bn], 1u); }
    if (s2 > 0.0f) { int bn = (int)(s2 * (float)NBIN); if (bn > NBIN-1) bn = NBIN-1; atomicAdd(&hb[bn], 1u); }
    if (s3 > 0.0f) { int bn = (int)(s3 * (float)NBIN); if (bn > NBIN-1) bn = NBIN-1; atomicAdd(&hb[bn], 1u); }
}

// ---------------- K2: top-1000 (counting sort) + class-aware NMS -------------
// dynamic smem layout (bytes):
//   [0,     16384)  buf  u64[2048]  unsorted candidate keys
//   [16384, 32768)  buf2 u64[2048]  sorted keys
//   [32768,160768)  mask u32[1000*32]   (phase>=6)
//     aliased: [32768,65536) fineH u32[8192], [65536,98304) offs u32[8192]
//   [160768,184768) sx1/sy1/sx2/sy2/sar f32[1000] + skd i32[1000]
//   [184768,188864) gsum u32[1024]  (threshold partials / row flags)
//   [188864,199104) kindBits u32[80*32]
#define SM_BUF2  16384
#define SM_MASK  32768
#define SM_FH    32768
#define SM_OFF   65536
#define SM_X1   160768
#define SM_Y1   164768
#define SM_X2   168768
#define SM_Y2   172768
#define SM_AR   176768
#define SM_KD   180768
#define SM_GS   184768
#define SM_KB   188864
#define SMEM_BYTES 199104

__global__ void __launch_bounds__(1024) k_topk_nms(float* __restrict__ out)
{
    const int b   = blockIdx.x;
    const int tid = threadIdx.x;

    extern __shared__ char sm[];
    unsigned long long* buf      = (unsigned long long*)sm;
    unsigned long long* buf2     = (unsigned long long*)(sm + SM_BUF2);
    unsigned*           mask     = (unsigned*)(sm + SM_MASK);
    unsigned*           fineH    = (unsigned*)(sm + SM_FH);
    unsigned*           offs     = (unsigned*)(sm + SM_OFF);
    float*              sx1      = (float*)(sm + SM_X1);
    float*              sy1      = (float*)(sm + SM_Y1);
    float*              sx2      = (float*)(sm + SM_X2);
    float*              sy2      = (float*)(sm + SM_Y2);
    float*              sar      = (float*)(sm + SM_AR);
    int*                skd      = (int*)(sm + SM_KD);
    unsigned*           gsum     = (unsigned*)(sm + SM_GS);
    unsigned*           kindBits = (unsigned*)(sm + SM_KB);

    __shared__ unsigned ssum[32], sWarp[32], sRem[32];
    __shared__ int s_t, s_cnt;

    const unsigned* hb = &g_hist[b * NBIN];

    // ---- phase T: threshold bin from global hist ----
    {
        unsigned s = 0;
        #pragma unroll
        for (int r = 0; r < 8; r++) s += hb[NBIN - 1 - (8 * tid + r)];
        gsum[tid] = s;
    }
    __syncthreads();
    if (tid < 32) {
        unsigned s = 0;
        #pragma unroll
        for (int q = 0; q < 32; q++) s += gsum[tid * 32 + q];
        ssum[tid] = s;
    }
    __syncthreads();
    if (tid == 0) {
        unsigned cum = 0;
        int t = 0;
        bool found = false;
        for (int w = 0; w < 32 && !found; w++) {
            if (cum + ssum[w] < KTOP) { cum += ssum[w]; continue; }
            for (int g = w * 32; g < w * 32 + 32 && !found; g++) {
                if (cum + gsum[g] < KTOP) { cum += gsum[g]; continue; }
                for (int r = g * 8; r < g * 8 + 8; r++) {
                    cum += hb[NBIN - 1 - r];
                    if (cum >= KTOP) { t = NBIN - 1 - r; found = true; break; }
                }
            }
        }
        s_t = found ? t : 0;
        s_cnt = 0;
    }
    __syncthreads();
    const int   t     = s_t;
    const float lo    = (float)t * (1.0f / (float)NBIN);
    const float scale = (float)NBIN / (1.0f - lo + 1e-6f);

    // ---- phase C: zero global hist for next call; compact + fine hist ----
    for (int i = tid; i < NBIN; i += 1024) {
        g_hist[b * NBIN + i] = 0u;    // safe: hb fully consumed in phase T
        fineH[i] = 0u;
    }
    __syncthreads();
    const float* sc_base = &g_score[b * NPOS];
    for (int i = tid; i < NPOS; i += 1024) {
        float sc = sc_base[i];
        if (sc > 0.0f) {
            int bin = (int)(sc * (float)NBIN);
            if (bin > NBIN - 1) bin = NBIN - 1;
            if (bin >= t) {
                int k = atomicAdd(&s_cnt, 1);
                if (k < CAP) {
                    buf[k] = ((unsigned long long)__float_as_uint(sc) << 32) |
                             (unsigned long long)(0xFFFFFFFFu - (unsigned)i);
                    int fb = (int)((sc - lo) * scale);
                    fb = max(0, min(NBIN - 1, fb));
                    atomicAdd(&fineH[fb], 1u);
                }
            }
        }
    }
    __syncthreads();
    const int C = min(s_cnt, CAP);

    // ---- phase S: exclusive scan over fine bins in DESCENDING fb order ----
    unsigned c8[8];
    unsigned tsum = 0;
    #pragma unroll
    for (int r = 0; r < 8; r++) {
        int fb = NBIN - 1 - (tid * 8 + r);
        c8[r] = fineH[fb];
        tsum += c8[r];
    }
    {
        unsigned lane = tid & 31, wrp = tid >> 5;
        unsigned v = tsum;
        #pragma unroll
        for (int o = 1; o < 32; o <<= 1) {
            unsigned u = __shfl_up_sync(0xFFFFFFFFu, v, o);
            if (lane >= o) v += u;
        }
        unsigned wexcl = v - tsum;
        if (lane == 31) sWarp[wrp] = v;
        __syncthreads();
        if (tid < 32) {
            unsigned w0 = sWarp[tid];
            unsigned vv = w0;
            #pragma unroll
            for (int o = 1; o < 32; o <<= 1) {
                unsigned u = __shfl_up_sync(0xFFFFFFFFu, vv, o);
                if (tid >= (unsigned)o) vv += u;
            }
            sWarp[tid] = vv - w0;
        }
        __syncthreads();
        unsigned run = sWarp[wrp] + wexcl;
        #pragma unroll
        for (int r = 0; r < 8; r++) {
            int fb = NBIN - 1 - (tid * 8 + r);
            offs[fb] = run;
            run += c8[r];
        }
    }
    __syncthreads();

    // ---- phase X: scatter to sorted positions ----
    for (int k = tid; k < C; k += 1024) {
        unsigned long long key = buf[k];
        float sc = __uint_as_float((unsigned)(key >> 32));
        int fb = (int)((sc - lo) * scale);
        fb = max(0, min(NBIN - 1, fb));
        unsigned slot = atomicAdd(&offs[fb], 1u);
        buf2[slot] = key;
    }
    __syncthreads();

    // ---- phase F: fix intra-bin order (tiny insertion sorts) + zero kindBits
    for (int fb = tid; fb < NBIN; fb += 1024) {
        unsigned c = fineH[fb];
        if (c >= 2) {
            unsigned st = offs[fb] - c;
            for (unsigned a = st + 1; a < st + c; a++) {
                unsigned long long kv = buf2[a];
                unsigned p = a;
                while (p > st && buf2[p - 1] < kv) { buf2[p] = buf2[p - 1]; p--; }
                buf2[p] = kv;
            }
        }
    }
    for (int i = tid; i < NCLS * 32; i += 1024) kindBits[i] = 0u;
    __syncthreads();

    // ---- phase 5: emit cols 0..4, stage NMS data, class bitmasks ----
    if (tid < KTOP) {
        int i = tid;
        unsigned long long key = (i < C) ? buf2[i] : 0ULL;
        unsigned pos = 0xFFFFFFFFu - (unsigned)(key & 0xFFFFFFFFull);
        if (key == 0ULL) pos = 0;
        int src = b * NPOS + (int)pos;
        float4 bx = g_boxes[src];
        int    kd = g_kind[src];

        int row = b * KTOP + i;
        out[row * 6 + 0] = bx.x;
        out[row * 6 + 1] = bx.y;
        out[row * 6 + 2] = bx.z;
        out[row * 6 + 3] = bx.w;
        out[row * 6 + 4] = (float)kd;

        sx1[i] = bx.x; sy1[i] = bx.y; sx2[i] = bx.z; sy2[i] = bx.w;
        sar[i] = fmaxf(bx.z - bx.x, 0.0f) * fmaxf(bx.w - bx.y, 0.0f);
        skd[i] = kd;
        atomicOr(&kindBits[kd * 32 + (i >> 5)], 1u << (i & 31));
    }
    __syncthreads();

    // ---- phase 6: suppression bitmask, gated by same-class membership ----
    for (int task = tid; task < KTOP * 32; task += 1024) {
        int i = task >> 5;
        int w = task & 31;
        int kd = skd[i];
        unsigned cand = kindBits[kd * 32 + w];
        int iw = i >> 5;
        if (w < iw)       cand = 0u;
        else if (w == iw) cand &= ~((2u << (i & 31)) - 1u);
        unsigned bits = 0u;
        if (cand) {
            float x1 = sx1[i], y1 = sy1[i], x2 = sx2[i], y2 = sy2[i], ai = sar[i];
            do {
                int jj = __ffs(cand) - 1;
                cand &= cand - 1u;
                int j = w * 32 + jj;
                float xx1 = fmaxf(x1, sx1[j]);
                float yy1 = fmaxf(y1, sy1[j]);
                float xx2 = fminf(x2, sx2[j]);
                float yy2 = fminf(y2, sy2[j]);
                float inter = fmaxf(xx2 - xx1, 0.0f) * fmaxf(yy2 - yy1, 0.0f);
                float iou = inter / (((ai + sar[j]) - inter) + 1e-9f);
                if (iou > IOU_TH) bits |= (1u << jj);
            } while (cand);
        }
        mask[i * 32 + w] = bits;
    }
    __syncthreads();

    // ---- phase 7: row-nonzero flags ----
    if (tid < KTOP) {
        unsigned nz = 0u;
        #pragma unroll 8
        for (int w = 0; w < 32; w++) nz |= mask[tid * 32 + w];
        gsum[tid] = nz;
    }
    __syncthreads();

    // ---- phase 8: greedy scan over nonzero rows only (warp 0) ----
    if (tid < 32) {
        unsigned removed = 0u;
        for (int base = 0; base < KTOP; base += 32) {
            int r0 = base + tid;
            unsigned f = (r0 < KTOP) ? gsum[r0] : 0u;
            unsigned bal = __ballot_sync(0xFFFFFFFFu, f != 0u);
            while (bal) {
                int r = base + __ffs(bal) - 1;
                bal &= bal - 1u;
                unsigned rb = __shfl_sync(0xFFFFFFFFu, removed, r >> 5);
                if (!((rb >> (r & 31)) & 1u))
                    removed |= mask[r * 32 + tid];
            }
        }
        sRem[tid] = removed;
    }
    __syncthreads();

    // ---- phase 9: final scores ----
    if (tid < KTOP) {
        int i = tid;
        bool kept = !((sRem[i >> 5] >> (i & 31)) & 1u);
        float sc = (i < C) ? __uint_as_float((unsigned)(buf2[i] >> 32)) : 0.0f;
        out[(b * KTOP + i) * 6 + 5] = (kept && sc > 0.0f) ? sc : 0.0f;
    }
}

// ---------------- launch ----------------
extern "C" void kernel_launch(void* const* d_in, const int* in_sizes, int n_in,
                              void* d_out, int out_size)
{
    static const int hw[5] = { 16384, 4096, 1024, 256, 64 };
    const float* clsP[5] = { 0, 0, 0, 0, 0 };
    const float* regP[5] = { 0, 0, 0, 0, 0 };
    bool cntSeen[5] = { false, false, false, false, false };

    for (int i = 0; i < n_in; i++) {
        long long s = in_sizes[i];
        bool matched = false;
        for (int l = 0; l < 5 && !matched; l++)
            if (s == (long long)NB * NCLS * hw[l]) { clsP[l] = (const float*)d_in[i]; matched = true; }
        if (matched) continue;
        for (int l = 0; l < 5 && !matched; l++)
            if (s == (long long)NB * hw[l] && !cntSeen[l]) { cntSeen[l] = true; matched = true; }
        if (matched) continue;
        for (int l = 0; l < 5 && !matched; l++)
            if (s == (long long)NB * 4 * hw[l] && !regP[l]) { regP[l] = (const float*)d_in[i]; matched = true; }
    }

    float* out = (float*)d_out;

    cudaFuncSetAttribute(k_topk_nms, cudaFuncAttributeMaxDynamicSharedMemorySize, SMEM_BYTES);

    dim3 g1((NG + 127) / 128, NB);
    k_decode<<<g1, 128>>>(clsP[0], clsP[1], clsP[2], clsP[3], clsP[4],
                          regP[0], regP[1], regP[2], regP[3], regP[4]);
    k_topk_nms<<<NB, 1024, SMEM_BYTES>>>(out);
}

// round 6
// speedup vs baseline: 5.7389x; 1.0570x over previous
#include <cuda_runtime.h>
#include <cstdint>

#define NB     8
#define NPOS   21824
#define NG     (NPOS / 4)
#define NCLS   80
#define KTOP   1000
#define NBIN   8192
#define CAP    2048
#define IOU_TH 0.5f
#define MPITCH 33            // padded mask row pitch (words) -> conflict-free both ways

// ---------------- scratch ----------------
__device__ __align__(16) float g_score[NB * NPOS];
__device__ __align__(16) int   g_kind [NB * NPOS];
__device__ float4              g_boxes[NB * NPOS];
__device__ unsigned            g_hist [NB * NBIN];   // zero at load; K2 re-zeros

// ---------------- K1: class max/argmax + decode + global score histogram -----
__global__ void k_decode(
    const float* __restrict__ c0, const float* __restrict__ c1,
    const float* __restrict__ c2, const float* __restrict__ c3,
    const float* __restrict__ c4,
    const float* __restrict__ r0, const float* __restrict__ r1,
    const float* __restrict__ r2, const float* __restrict__ r3,
    const float* __restrict__ r4)
{
    int g = blockIdx.x * blockDim.x + threadIdx.x;
    if (g >= NG) return;
    int b   = blockIdx.y;
    int pos = g << 2;

    int lvl, local, logw;
    float stride;
    if      (pos < 16384) { lvl = 0; local = pos;         logw = 7; stride = 8.f;   }
    else if (pos < 20480) { lvl = 1; local = pos - 16384; logw = 6; stride = 16.f;  }
    else if (pos < 21504) { lvl = 2; local = pos - 20480; logw = 5; stride = 32.f;  }
    else if (pos < 21760) { lvl = 3; local = pos - 21504; logw = 4; stride = 64.f;  }
    else                  { lvl = 4; local = pos - 21760; logw = 3; stride = 128.f; }
    int hw    = 1 << (2 * logw);
    int cstep = hw >> 2;

    const float* clsA[5] = { c0, c1, c2, c3, c4 };
    const float* regA[5] = { r0, r1, r2, r3, r4 };

    const float4* cls = (const float4*)(clsA[lvl] + (size_t)b * NCLS * hw + local);
    float4 bv = cls[0];
    int k0 = 0, k1 = 0, k2 = 0, k3 = 0;
    #pragma unroll 8
    for (int c = 1; c < NCLS; c++) {
        float4 v = cls[(size_t)c * cstep];
        if (v.x > bv.x) { bv.x = v.x; k0 = c; }
        if (v.y > bv.y) { bv.y = v.y; k1 = c; }
        if (v.z > bv.z) { bv.z = v.z; k2 = c; }
        if (v.w > bv.w) { bv.w = v.w; k3 = c; }
    }

    const float4* rg = (const float4*)(regA[lvl] + (size_t)b * 4 * hw + local);
    float4 dl4 = rg[0];
    float4 dt4 = rg[cstep];
    float4 dr4 = rg[2 * cstep];
    float4 db4 = rg[3 * cstep];

    int w = 1 << logw;
    int y = local >> logw;
    int x = local & (w - 1);
    float cy = ((float)y + 0.5f) * stride;

    int o = b * NPOS + pos;
    {
        float cx = ((float)(x + 0) + 0.5f) * stride;
        g_boxes[o + 0] = make_float4(cx - dl4.x * stride, cy - dt4.x * stride,
                                     cx + dr4.x * stride, cy + db4.x * stride);
        cx = ((float)(x + 1) + 0.5f) * stride;
        g_boxes[o + 1] = make_float4(cx - dl4.y * stride, cy - dt4.y * stride,
                                     cx + dr4.y * stride, cy + db4.y * stride);
        cx = ((float)(x + 2) + 0.5f) * stride;
        g_boxes[o + 2] = make_float4(cx - dl4.z * stride, cy - dt4.z * stride,
                                     cx + dr4.z * stride, cy + db4.z * stride);
        cx = ((float)(x + 3) + 0.5f) * stride;
        g_boxes[o + 3] = make_float4(cx - dl4.w * stride, cy - dt4.w * stride,
                                     cx + dr4.w * stride, cy + db4.w * stride);
    }
    float s0 = (bv.x > 0.05f) ? bv.x : 0.0f;
    float s1 = (bv.y > 0.05f) ? bv.y : 0.0f;
    float s2 = (bv.z > 0.05f) ? bv.z : 0.0f;
    float s3 = (bv.w > 0.05f) ? bv.w : 0.0f;
    *(float4*)&g_score[o] = make_float4(s0, s1, s2, s3);
    *(int4*)&g_kind[o]    = make_int4(k0, k1, k2, k3);

    unsigned* hb = &g_hist[b * NBIN];
    if (s0 > 0.0f) { int bn = (int)(s0 * (float)NBIN); if (bn > NBIN-1) bn = NBIN-1; atomicAdd(&hb[bn], 1u); }
    if (s1 > 0.0f) { int bn = (int)(s1 * (float)NBIN); if (bn > NBIN-1) bn = NBIN-1; atomicAdd(&hb[bn], 1u); }
    if (s2 > 0.0f) { int bn = (int)(s2 * (float)NBIN); if (bn > NBIN-1) bn = NBIN-1; atomicAdd(&hb[bn], 1u); }
    if (s3 > 0.0f) { int bn = (int)(s3 * (float)NBIN); if (bn > NBIN-1) bn = NBIN-1; atomicAdd(&hb[bn], 1u); }
}

// ---------------- K2: top-1000 (counting sort) + class-aware NMS -------------
// dynamic smem layout (bytes):
//   [0,     16384)  buf  u64[2048]      unsorted candidate keys
//   [16384, 32768)  buf2 u64[2048]      sorted keys
//   [32768,164768)  mask u32[1000*33]   (phase>=6; padded pitch 33)
//     aliased: [32768,65536) fineH u32[8192] / hist copy
//              [65536,98304) offs u32[8192]
//   [164768,188768) sx1/sy1/sx2/sy2/sar f32[1000] + skd i32[1000]
//   [188768,192864) gsum u32[1024]  (threshold partials, later row-nonzero flags)
//   [192864,203104) kindBits u32[80*32]
#define SM_BUF2  16384
#define SM_MASK  32768
#define SM_FH    32768
#define SM_OFF   65536
#define SM_X1   164768
#define SM_Y1   168768
#define SM_X2   172768
#define SM_Y2   176768
#define SM_AR   180768
#define SM_KD   184768
#define SM_GS   188768
#define SM_KB   192864
#define SMEM_BYTES 203104

__global__ void __launch_bounds__(1024) k_topk_nms(float* __restrict__ out)
{
    const int b   = blockIdx.x;
    const int tid = threadIdx.x;

    extern __shared__ char sm[];
    unsigned long long* buf      = (unsigned long long*)sm;
    unsigned long long* buf2     = (unsigned long long*)(sm + SM_BUF2);
    unsigned*           mask     = (unsigned*)(sm + SM_MASK);
    unsigned*           fineH    = (unsigned*)(sm + SM_FH);
    unsigned*           offs     = (unsigned*)(sm + SM_OFF);
    float*              sx1      = (float*)(sm + SM_X1);
    float*              sy1      = (float*)(sm + SM_Y1);
    float*              sx2      = (float*)(sm + SM_X2);
    float*              sy2      = (float*)(sm + SM_Y2);
    float*              sar      = (float*)(sm + SM_AR);
    int*                skd      = (int*)(sm + SM_KD);
    unsigned*           gsum     = (unsigned*)(sm + SM_GS);
    unsigned*           kindBits = (unsigned*)(sm + SM_KB);

    __shared__ unsigned ssum[32], sWarp[32], sRem[32];
    __shared__ int s_t, s_cnt;

    const unsigned* hb = &g_hist[b * NBIN];

    // ---- phase T: threshold bin from global hist (stash raw hist in smem) ----
    {
        unsigned s = 0;
        #pragma unroll
        for (int r = 0; r < 8; r++) {
            unsigned h = hb[NBIN - 1 - (8 * tid + r)];
            fineH[NBIN - 1 - (8 * tid + r)] = h;   // smem copy for serial search
            s += h;
        }
        gsum[tid] = s;
    }
    __syncthreads();
    if (tid < 32) {
        unsigned s = 0;
        #pragma unroll
        for (int q = 0; q < 32; q++) s += gsum[tid * 32 + q];
        ssum[tid] = s;
    }
    __syncthreads();
    if (tid == 0) {
        unsigned cum = 0;
        int t = 0;
        bool found = false;
        for (int w = 0; w < 32 && !found; w++) {
            if (cum + ssum[w] < KTOP) { cum += ssum[w]; continue; }
            for (int g = w * 32; g < w * 32 + 32 && !found; g++) {
                if (cum + gsum[g] < KTOP) { cum += gsum[g]; continue; }
                for (int r = g * 8; r < g * 8 + 8; r++) {
                    cum += fineH[NBIN - 1 - r];
                    if (cum >= KTOP) { t = NBIN - 1 - r; found = true; break; }
                }
            }
        }
        s_t = found ? t : 0;
        s_cnt = 0;
    }
    __syncthreads();
    const int   t     = s_t;
    const float lo    = (float)t * (1.0f / (float)NBIN);
    const float scale = (float)NBIN / (1.0f - lo + 1e-6f);

    // ---- phase C: zero global hist for next call; compact + fine hist ----
    for (int i = tid; i < NBIN; i += 1024) {
        g_hist[b * NBIN + i] = 0u;
        fineH[i] = 0u;
    }
    __syncthreads();
    const float* sc_base = &g_score[b * NPOS];
    for (int i = tid; i < NPOS; i += 1024) {
        float sc = sc_base[i];
        if (sc > 0.0f) {
            int bin = (int)(sc * (float)NBIN);
            if (bin > NBIN - 1) bin = NBIN - 1;
            if (bin >= t) {
                int k = atomicAdd(&s_cnt, 1);
                if (k < CAP) {
                    buf[k] = ((unsigned long long)__float_as_uint(sc) << 32) |
                             (unsigned long long)(0xFFFFFFFFu - (unsigned)i);
                    int fb = (int)((sc - lo) * scale);
                    fb = max(0, min(NBIN - 1, fb));
                    atomicAdd(&fineH[fb], 1u);
                }
            }
        }
    }
    __syncthreads();
    const int C = min(s_cnt, CAP);

    // ---- phase S: exclusive scan over fine bins in DESCENDING fb order ----
    unsigned c8[8];
    unsigned tsum = 0;
    #pragma unroll
    for (int r = 0; r < 8; r++) {
        int fb = NBIN - 1 - (tid * 8 + r);
        c8[r] = fineH[fb];
        tsum += c8[r];
    }
    {
        unsigned lane = tid & 31, wrp = tid >> 5;
        unsigned v = tsum;
        #pragma unroll
        for (int o = 1; o < 32; o <<= 1) {
            unsigned u = __shfl_up_sync(0xFFFFFFFFu, v, o);
            if (lane >= o) v += u;
        }
        unsigned wexcl = v - tsum;
        if (lane == 31) sWarp[wrp] = v;
        __syncthreads();
        if (tid < 32) {
            unsigned w0 = sWarp[tid];
            unsigned vv = w0;
            #pragma unroll
            for (int o = 1; o < 32; o <<= 1) {
                unsigned u = __shfl_up_sync(0xFFFFFFFFu, vv, o);
                if (tid >= (unsigned)o) vv += u;
            }
            sWarp[tid] = vv - w0;
        }
        __syncthreads();
        unsigned run = sWarp[wrp] + wexcl;
        #pragma unroll
        for (int r = 0; r < 8; r++) {
            int fb = NBIN - 1 - (tid * 8 + r);
            offs[fb] = run;
            run += c8[r];
        }
    }
    __syncthreads();

    // ---- phase X: scatter to sorted positions ----
    for (int k = tid; k < C; k += 1024) {
        unsigned long long key = buf[k];
        float sc = __uint_as_float((unsigned)(key >> 32));
        int fb = (int)((sc - lo) * scale);
        fb = max(0, min(NBIN - 1, fb));
        unsigned slot = atomicAdd(&offs[fb], 1u);
        buf2[slot] = key;
    }
    __syncthreads();

    // ---- phase F: fix intra-bin order; zero kindBits + row flags ----
    for (int fb = tid; fb < NBIN; fb += 1024) {
        unsigned c = fineH[fb];
        if (c >= 2) {
            unsigned st = offs[fb] - c;
            for (unsigned a = st + 1; a < st + c; a++) {
                unsigned long long kv = buf2[a];
                unsigned p = a;
                while (p > st && buf2[p - 1] < kv) { buf2[p] = buf2[p - 1]; p--; }
                buf2[p] = kv;
            }
        }
    }
    for (int i = tid; i < NCLS * 32; i += 1024) kindBits[i] = 0u;
    gsum[tid] = 0u;                       // row-nonzero flags (only [0,KTOP) used)
    __syncthreads();

    // ---- phase 5: emit cols 0..4, stage NMS data, class bitmasks ----
    if (tid < KTOP) {
        int i = tid;
        unsigned long long key = (i < C) ? buf2[i] : 0ULL;
        unsigned pos = 0xFFFFFFFFu - (unsigned)(key & 0xFFFFFFFFull);
        if (key == 0ULL) pos = 0;
        int src = b * NPOS + (int)pos;
        float4 bx = g_boxes[src];
        int    kd = g_kind[src];

        int row = b * KTOP + i;
        out[row * 6 + 0] = bx.x;
        out[row * 6 + 1] = bx.y;
        out[row * 6 + 2] = bx.z;
        out[row * 6 + 3] = bx.w;
        out[row * 6 + 4] = (float)kd;

        sx1[i] = bx.x; sy1[i] = bx.y; sx2[i] = bx.z; sy2[i] = bx.w;
        sar[i] = fmaxf(bx.z - bx.x, 0.0f) * fmaxf(bx.w - bx.y, 0.0f);
        skd[i] = kd;
        atomicOr(&kindBits[kd * 32 + (i >> 5)], 1u << (i & 31));
    }
    __syncthreads();

    // ---- phase 6: suppression bitmask (padded pitch), inline row flags ----
    for (int task = tid; task < KTOP * 32; task += 1024) {
        int i = task >> 5;
        int w = task & 31;
        int kd = skd[i];
        unsigned cand = kindBits[kd * 32 + w];
        int iw = i >> 5;
        if (w < iw)       cand = 0u;
        else if (w == iw) cand &= ~((2u << (i & 31)) - 1u);
        unsigned bits = 0u;
        if (cand) {
            float x1 = sx1[i], y1 = sy1[i], x2 = sx2[i], y2 = sy2[i], ai = sar[i];
            do {
                int jj = __ffs(cand) - 1;
                cand &= cand - 1u;
                int j = w * 32 + jj;
                float xx1 = fmaxf(x1, sx1[j]);
                float yy1 = fmaxf(y1, sy1[j]);
                float xx2 = fminf(x2, sx2[j]);
                float yy2 = fminf(y2, sy2[j]);
                float inter = fmaxf(xx2 - xx1, 0.0f) * fmaxf(yy2 - yy1, 0.0f);
                float iou = inter / (((ai + sar[j]) - inter) + 1e-9f);
                if (iou > IOU_TH) bits |= (1u << jj);
            } while (cand);
        }
        mask[i * MPITCH + w] = bits;
        if (bits) atomicOr(&gsum[i], 1u);   // rare
    }
    __syncthreads();

    // ---- phase 8: greedy scan over nonzero rows only (warp 0) ----
    if (tid < 32) {
        unsigned removed = 0u;
        for (int base = 0; base < KTOP; base += 32) {
            int r0 = base + tid;
            unsigned f = (r0 < KTOP) ? gsum[r0] : 0u;
            unsigned bal = __ballot_sync(0xFFFFFFFFu, f != 0u);
            while (bal) {
                int r = base + __ffs(bal) - 1;
                bal &= bal - 1u;
                unsigned rb = __shfl_sync(0xFFFFFFFFu, removed, r >> 5);
                if (!((rb >> (r & 31)) & 1u))
                    removed |= mask[r * MPITCH + tid];
            }
        }
        sRem[tid] = removed;
    }
    __syncthreads();

    // ---- phase 9: final scores ----
    if (tid < KTOP) {
        int i = tid;
        bool kept = !((sRem[i >> 5] >> (i & 31)) & 1u);
        float sc = (i < C) ? __uint_as_float((unsigned)(buf2[i] >> 32)) : 0.0f;
        out[(b * KTOP + i) * 6 + 5] = (kept && sc > 0.0f) ? sc : 0.0f;
    }
}

// ---------------- launch ----------------
extern "C" void kernel_launch(void* const* d_in, const int* in_sizes, int n_in,
                              void* d_out, int out_size)
{
    static const int hw[5] = { 16384, 4096, 1024, 256, 64 };
    const float* clsP[5] = { 0, 0, 0, 0, 0 };
    const float* regP[5] = { 0, 0, 0, 0, 0 };
    bool cntSeen[5] = { false, false, false, false, false };

    for (int i = 0; i < n_in; i++) {
        long long s = in_sizes[i];
        bool matched = false;
        for (int l = 0; l < 5 && !matched; l++)
            if (s == (long long)NB * NCLS * hw[l]) { clsP[l] = (const float*)d_in[i]; matched = true; }
        if (matched) continue;
        for (int l = 0; l < 5 && !matched; l++)
            if (s == (long long)NB * hw[l] && !cntSeen[l]) { cntSeen[l] = true; matched = true; }
        if (matched) continue;
        for (int l = 0; l < 5 && !matched; l++)
            if (s == (long long)NB * 4 * hw[l] && !regP[l]) { regP[l] = (const float*)d_in[i]; matched = true; }
    }

    float* out = (float*)d_out;

    cudaFuncSetAttribute(k_topk_nms, cudaFuncAttributeMaxDynamicSharedMemorySize, SMEM_BYTES);

    dim3 g1((NG + 127) / 128, NB);
    k_decode<<<g1, 128>>>(clsP[0], clsP[1], clsP[2], clsP[3], clsP[4],
                          regP[0], regP[1], regP[2], regP[3], regP[4]);
    k_topk_nms<<<NB, 1024, SMEM_BYTES>>>(out);
}